// round 10
// baseline (speedup 1.0000x reference)
#include <cuda_runtime.h>

#define BSZ 4
#define NH  16
#define TT  2048
#define DD  1024
#define DH  64

// scratch for q,k,v: [3][B][H][T][64] fp32 bits (tf32-pre-rounded), 100 MB
static __device__ float g_qkv[(size_t)3 * BSZ * NH * TT * DH];

__device__ __forceinline__ unsigned f2tf(float f) {
    unsigned u;
    asm("cvt.rna.tf32.f32 %0, %1;" : "=r"(u) : "f"(f));
    return u;
}

__device__ __forceinline__ void mma8(float* c,
                                     unsigned a0, unsigned a1, unsigned a2, unsigned a3,
                                     unsigned b0, unsigned b1) {
    asm volatile(
        "mma.sync.aligned.m16n8k8.row.col.f32.tf32.tf32.f32 "
        "{%0,%1,%2,%3},{%4,%5,%6,%7},{%8,%9},{%0,%1,%2,%3};"
        : "+f"(c[0]), "+f"(c[1]), "+f"(c[2]), "+f"(c[3])
        : "r"(a0), "r"(a1), "r"(a2), "r"(a3), "r"(b0), "r"(b1));
}

// ============================================================================
// Kernel 1: QKV projection + q/k normalization. (unchanged — proven)
// ============================================================================
__global__ __launch_bounds__(256, 2) void qkv_proj_kernel(const float* __restrict__ x,
                                                          const float* __restrict__ w) {
    __shared__ unsigned sX[32 * 264];  // [d][t] tf32, pad 8
    __shared__ unsigned sW[32 * 72];   // [d][e] tf32, pad 8

    const int t0  = blockIdx.x * 256;
    const int nbh = blockIdx.y;
    const int n   = nbh >> 6;
    const int b   = (nbh >> 4) & 3;
    const int hh  = nbh & 15;

    const float* xb = x + (size_t)b * DD * TT + t0;
    const float* wb = w + (size_t)(n * NH + hh) * DD * DH;

    const int tid  = threadIdx.x;
    const int lane = tid & 31;
    const int wid  = tid >> 5;
    const int grp  = lane >> 2;
    const int tig  = lane & 3;
    const int rb   = wid * 32;

    float acc[2][8][4];
#pragma unroll
    for (int mt = 0; mt < 2; mt++)
#pragma unroll
        for (int nt = 0; nt < 8; nt++)
            acc[mt][nt][0] = acc[mt][nt][1] = acc[mt][nt][2] = acc[mt][nt][3] = 0.f;

    for (int kt = 0; kt < DD; kt += 32) {
#pragma unroll
        for (int i = 0; i < 8; i++) {
            int idx = i * 256 + tid;
            int dd  = idx >> 6;
            int t4  = idx & 63;
            float4 v = *(const float4*)(xb + (size_t)(kt + dd) * TT + t4 * 4);
            uint4 u = make_uint4(f2tf(v.x), f2tf(v.y), f2tf(v.z), f2tf(v.w));
            *(uint4*)&sX[dd * 264 + t4 * 4] = u;
        }
#pragma unroll
        for (int i = 0; i < 2; i++) {
            int idx = i * 256 + tid;
            int dd  = idx >> 4;
            int e4  = idx & 15;
            float4 v = *(const float4*)(wb + (size_t)(kt + dd) * DH + e4 * 4);
            uint4 u = make_uint4(f2tf(v.x), f2tf(v.y), f2tf(v.z), f2tf(v.w));
            *(uint4*)&sW[dd * 72 + e4 * 4] = u;
        }
        __syncthreads();

#pragma unroll
        for (int ks = 0; ks < 4; ks++) {
            const int k0 = ks * 8;
            unsigned a[2][4];
#pragma unroll
            for (int mt = 0; mt < 2; mt++) {
                const int r = rb + mt * 16 + grp;
                a[mt][0] = sX[(k0 + tig) * 264 + r];
                a[mt][1] = sX[(k0 + tig) * 264 + r + 8];
                a[mt][2] = sX[(k0 + tig + 4) * 264 + r];
                a[mt][3] = sX[(k0 + tig + 4) * 264 + r + 8];
            }
#pragma unroll
            for (int nt = 0; nt < 8; nt++) {
                unsigned b0 = sW[(k0 + tig) * 72 + nt * 8 + grp];
                unsigned b1 = sW[(k0 + tig + 4) * 72 + nt * 8 + grp];
                mma8(acc[0][nt], a[0][0], a[0][1], a[0][2], a[0][3], b0, b1);
                mma8(acc[1][nt], a[1][0], a[1][1], a[1][2], a[1][3], b0, b1);
            }
        }
        __syncthreads();
    }

    if (n < 2) {
#pragma unroll
        for (int mt = 0; mt < 2; mt++) {
            float slo = 0.f, shi = 0.f;
#pragma unroll
            for (int nt = 0; nt < 8; nt++) {
                slo += acc[mt][nt][0] + acc[mt][nt][1];
                shi += acc[mt][nt][2] + acc[mt][nt][3];
            }
            slo += __shfl_xor_sync(~0u, slo, 1); slo += __shfl_xor_sync(~0u, slo, 2);
            shi += __shfl_xor_sync(~0u, shi, 1); shi += __shfl_xor_sync(~0u, shi, 2);
            float mlo = slo * (1.f / 64.f), mhi = shi * (1.f / 64.f);
            float vlo = 0.f, vhi = 0.f;
#pragma unroll
            for (int nt = 0; nt < 8; nt++) {
                float d0 = acc[mt][nt][0] - mlo, d1 = acc[mt][nt][1] - mlo;
                float d2 = acc[mt][nt][2] - mhi, d3 = acc[mt][nt][3] - mhi;
                vlo += d0 * d0 + d1 * d1;
                vhi += d2 * d2 + d3 * d3;
            }
            vlo += __shfl_xor_sync(~0u, vlo, 1); vlo += __shfl_xor_sync(~0u, vlo, 2);
            vhi += __shfl_xor_sync(~0u, vhi, 1); vhi += __shfl_xor_sync(~0u, vhi, 2);
            float ilo = 1.f / (sqrtf(vlo * (1.f / 63.f)) + 1e-5f);
            float ihi = 1.f / (sqrtf(vhi * (1.f / 63.f)) + 1e-5f);
#pragma unroll
            for (int nt = 0; nt < 8; nt++) {
                acc[mt][nt][0] = (acc[mt][nt][0] - mlo) * ilo;
                acc[mt][nt][1] = (acc[mt][nt][1] - mlo) * ilo;
                acc[mt][nt][2] = (acc[mt][nt][2] - mhi) * ihi;
                acc[mt][nt][3] = (acc[mt][nt][3] - mhi) * ihi;
            }
        }
    }

    float* dst = g_qkv + (((size_t)n * BSZ + b) * NH + hh) * (size_t)TT * DH;
#pragma unroll
    for (int mt = 0; mt < 2; mt++) {
        const int rlo = t0 + rb + mt * 16 + grp;
        const int rhi = rlo + 8;
#pragma unroll
        for (int nt = 0; nt < 8; nt++) {
            int e = nt * 8 + 2 * tig;
            *(float2*)(dst + (size_t)rlo * DH + e) =
                make_float2(__uint_as_float(f2tf(acc[mt][nt][0])),
                            __uint_as_float(f2tf(acc[mt][nt][1])));
            *(float2*)(dst + (size_t)rhi * DH + e) =
                make_float2(__uint_as_float(f2tf(acc[mt][nt][2])),
                            __uint_as_float(f2tf(acc[mt][nt][3])));
        }
    }
}

// ============================================================================
// Kernel 2: flash attention, no-max softmax (|S| <= 7.9 guaranteed by q/k
// normalization => exp() is fp32-safe unshifted).
// grid (T/128, B*H), 256 threads, 2 blocks/SM (regs<=128, smem 104KB).
// Warp owns 16 q-rows x 64 s-cols. K tile stored with d-pair permutation so
// B fragments load as one LDS.64.
// ============================================================================
#define SMEM2_WORDS ((128 + 64 + 64 + 128) * 68)

__global__ __launch_bounds__(256, 2) void attn_kernel(float* __restrict__ out) {
    extern __shared__ unsigned sm[];
    unsigned* sQ = sm;                 // [128][68] tf32 bits
    unsigned* sK = sQ + 128 * 68;      // [64][68]  tf32 bits, d-pair-permuted
    unsigned* sV = sK + 64 * 68;       // [64][68]  tf32 bits
    unsigned* sP = sV + 64 * 68;       // [128][68] fp32 bits (tf32-trunc by HW)

    const int t0 = blockIdx.x * 128;
    const int b  = blockIdx.y >> 4;
    const int hh = blockIdx.y & 15;

    const size_t base = (((size_t)b) * NH + hh) * (size_t)TT * DH;
    const size_t pl   = (size_t)BSZ * NH * TT * DH;
    const float* Qg = g_qkv + base;
    const float* Kg = g_qkv + pl + base;
    const float* Vg = g_qkv + 2 * pl + base;

    const int tid  = threadIdx.x;
    const int lane = tid & 31;
    const int wid  = tid >> 5;
    const int grp  = lane >> 2;
    const int tig  = lane & 3;
    const int rb   = wid * 16;

    // load Q tile once: 128x64 = 2048 uint4, 8 per thread (already tf32 bits)
    {
        const uint4* Qg4 = (const uint4*)(Qg + (size_t)t0 * DH);
#pragma unroll
        for (int i = 0; i < 8; i++) {
            int idx = i * 256 + tid;
            int r = idx >> 4, e4 = idx & 15;
            *(uint4*)&sQ[r * 68 + e4 * 4] = Qg4[idx];
        }
    }

    float o[8][4];
#pragma unroll
    for (int nt = 0; nt < 8; nt++) { o[nt][0] = o[nt][1] = o[nt][2] = o[nt][3] = 0.f; }
    float llo = 0.f, lhi = 0.f;

    for (int s0 = 0; s0 < TT; s0 += 64) {
        // K tile with d-pair permutation: logical d (within 8-group dd) goes to
        // physical pos (dd&3)*2 + (dd>>2). uint4 covers dd = (d4&1)*4 + j,
        // j=0..3 -> pos = j*2 + (d4&1) within group d4>>1.
        {
            const uint4* Kg4 = (const uint4*)(Kg + (size_t)s0 * DH);
            const uint4* Vg4 = (const uint4*)(Vg + (size_t)s0 * DH);
#pragma unroll
            for (int i = 0; i < 4; i++) {
                int idx = i * 256 + tid;
                int r = idx >> 4, d4 = idx & 15;
                uint4 v = Kg4[idx];
                unsigned* kb = &sK[r * 68 + ((d4 >> 1) << 3) + (d4 & 1)];
                kb[0] = v.x; kb[2] = v.y; kb[4] = v.z; kb[6] = v.w;
                *(uint4*)&sV[r * 68 + d4 * 4] = Vg4[idx];
            }
        }
        __syncthreads();  // K,V visible (first iter: also covers Q load)

        // S = Q K^T  (16 rows x 64 s-cols per warp); B pair via LDS.64
        float sa[8][4];
#pragma unroll
        for (int nt = 0; nt < 8; nt++) { sa[nt][0] = sa[nt][1] = sa[nt][2] = sa[nt][3] = 0.f; }
#pragma unroll
        for (int ks = 0; ks < 8; ks++) {
            const int k0 = ks * 8;
            unsigned a0 = sQ[(rb + grp) * 68 + k0 + tig];
            unsigned a1 = sQ[(rb + grp + 8) * 68 + k0 + tig];
            unsigned a2 = sQ[(rb + grp) * 68 + k0 + tig + 4];
            unsigned a3 = sQ[(rb + grp + 8) * 68 + k0 + tig + 4];
#pragma unroll
            for (int nt = 0; nt < 8; nt++) {
                uint2 bb = *(const uint2*)&sK[(nt * 8 + grp) * 68 + k0 + 2 * tig];
                mma8(sa[nt], a0, a1, a2, a3, bb.x, bb.y);
            }
        }

        // unshifted softmax accumulation (scale 1/8); P -> sP raw bits
        float rslo = 0.f, rshi = 0.f;
#pragma unroll
        for (int nt = 0; nt < 8; nt++) {
            sa[nt][0] = __expf(sa[nt][0] * 0.125f);
            sa[nt][1] = __expf(sa[nt][1] * 0.125f);
            sa[nt][2] = __expf(sa[nt][2] * 0.125f);
            sa[nt][3] = __expf(sa[nt][3] * 0.125f);
            rslo += sa[nt][0] + sa[nt][1];
            rshi += sa[nt][2] + sa[nt][3];
            int sc = nt * 8 + 2 * tig;
            *(uint2*)&sP[(rb + grp) * 68 + sc] =
                make_uint2(__float_as_uint(sa[nt][0]), __float_as_uint(sa[nt][1]));
            *(uint2*)&sP[(rb + grp + 8) * 68 + sc] =
                make_uint2(__float_as_uint(sa[nt][2]), __float_as_uint(sa[nt][3]));
        }
        rslo += __shfl_xor_sync(~0u, rslo, 1); rslo += __shfl_xor_sync(~0u, rslo, 2);
        rshi += __shfl_xor_sync(~0u, rshi, 1); rshi += __shfl_xor_sync(~0u, rshi, 2);
        llo += rslo;
        lhi += rshi;
        __syncwarp();

        // O += P V  (no rescale needed — no running max)
#pragma unroll
        for (int ks = 0; ks < 8; ks++) {
            const int k0 = ks * 8;
            unsigned a0 = sP[(rb + grp) * 68 + k0 + tig];
            unsigned a1 = sP[(rb + grp + 8) * 68 + k0 + tig];
            unsigned a2 = sP[(rb + grp) * 68 + k0 + tig + 4];
            unsigned a3 = sP[(rb + grp + 8) * 68 + k0 + tig + 4];
#pragma unroll
            for (int nt = 0; nt < 8; nt++) {
                unsigned b0 = sV[(k0 + tig) * 68 + nt * 8 + grp];
                unsigned b1 = sV[(k0 + tig + 4) * 68 + nt * 8 + grp];
                mma8(o[nt], a0, a1, a2, a3, b0, b1);
            }
        }
        __syncthreads();  // all warps done with sK/sV before next overwrite
    }

    // epilogue: divide by l, write transposed out[b, h*64+e, t]
    float ilo = 1.f / llo, ihi = 1.f / lhi;
    float* ob = out + ((size_t)b * DD + hh * DH) * TT;
    const int rlo = t0 + rb + grp;
    const int rhi = rlo + 8;
#pragma unroll
    for (int nt = 0; nt < 8; nt++) {
        int e = nt * 8 + 2 * tig;
        ob[(size_t)e * TT + rlo]       = o[nt][0] * ilo;
        ob[(size_t)(e + 1) * TT + rlo] = o[nt][1] * ilo;
        ob[(size_t)e * TT + rhi]       = o[nt][2] * ihi;
        ob[(size_t)(e + 1) * TT + rhi] = o[nt][3] * ihi;
    }
}

extern "C" void kernel_launch(void* const* d_in, const int* in_sizes, int n_in,
                              void* d_out, int out_size) {
    (void)in_sizes; (void)n_in; (void)out_size;
    const float* x   = (const float*)d_in[0];   // [4,1024,2048] fp32
    const float* qkv = (const float*)d_in[1];   // [3,16,1024,64] fp32
    float* out = (float*)d_out;                 // [4,1024,2048] fp32

    qkv_proj_kernel<<<dim3(TT / 256, 3 * BSZ * NH), 256>>>(x, qkv);

    const int smem2 = SMEM2_WORDS * 4;  // 104448 B -> 2 blocks/SM
    cudaFuncSetAttribute(attn_kernel, cudaFuncAttributeMaxDynamicSharedMemorySize, smem2);
    attn_kernel<<<dim3(TT / 128, BSZ * NH), 256, smem2>>>(out);
}

// round 11
// speedup vs baseline: 1.1931x; 1.1931x over previous
#include <cuda_runtime.h>

#define BSZ 4
#define NH  16
#define TT  2048
#define DD  1024
#define DH  64

// scratch: [3][B][H]... Q: [T][64], K: TRANSPOSED [64][T], V: [T][64]; tf32 bits
static __device__ float g_qkv[(size_t)3 * BSZ * NH * TT * DH];

__device__ __forceinline__ unsigned f2tf(float f) {
    unsigned u;
    asm("cvt.rna.tf32.f32 %0, %1;" : "=r"(u) : "f"(f));
    return u;
}

__device__ __forceinline__ void mma8(float* c,
                                     unsigned a0, unsigned a1, unsigned a2, unsigned a3,
                                     unsigned b0, unsigned b1) {
    asm volatile(
        "mma.sync.aligned.m16n8k8.row.col.f32.tf32.tf32.f32 "
        "{%0,%1,%2,%3},{%4,%5,%6,%7},{%8,%9},{%0,%1,%2,%3};"
        : "+f"(c[0]), "+f"(c[1]), "+f"(c[2]), "+f"(c[3])
        : "r"(a0), "r"(a1), "r"(a2), "r"(a3), "r"(b0), "r"(b1));
}

// column permutation for the 4-nt LDS.128 trick: x = logical col (0..63)
__device__ __forceinline__ int qperm(int x) {
    return ((x >> 3) & 3) | (((x >> 1) & 3) << 2) | ((x & 1) << 4) | ((x >> 5) << 5);
}

// ============================================================================
// Kernel 1: QKV projection + q/k normalization. K written TRANSPOSED [e][t].
// ============================================================================
__global__ __launch_bounds__(256, 2) void qkv_proj_kernel(const float* __restrict__ x,
                                                          const float* __restrict__ w) {
    __shared__ unsigned sX[32 * 264];  // [d][t] tf32, pad 8
    __shared__ unsigned sW[32 * 72];   // [d][e] tf32, pad 8

    const int t0  = blockIdx.x * 256;
    const int nbh = blockIdx.y;
    const int n   = nbh >> 6;
    const int b   = (nbh >> 4) & 3;
    const int hh  = nbh & 15;

    const float* xb = x + (size_t)b * DD * TT + t0;
    const float* wb = w + (size_t)(n * NH + hh) * DD * DH;

    const int tid  = threadIdx.x;
    const int lane = tid & 31;
    const int wid  = tid >> 5;
    const int grp  = lane >> 2;
    const int tig  = lane & 3;
    const int rb   = wid * 32;

    float acc[2][8][4];
#pragma unroll
    for (int mt = 0; mt < 2; mt++)
#pragma unroll
        for (int nt = 0; nt < 8; nt++)
            acc[mt][nt][0] = acc[mt][nt][1] = acc[mt][nt][2] = acc[mt][nt][3] = 0.f;

    for (int kt = 0; kt < DD; kt += 32) {
#pragma unroll
        for (int i = 0; i < 8; i++) {
            int idx = i * 256 + tid;
            int dd  = idx >> 6;
            int t4  = idx & 63;
            float4 v = *(const float4*)(xb + (size_t)(kt + dd) * TT + t4 * 4);
            uint4 u = make_uint4(f2tf(v.x), f2tf(v.y), f2tf(v.z), f2tf(v.w));
            *(uint4*)&sX[dd * 264 + t4 * 4] = u;
        }
#pragma unroll
        for (int i = 0; i < 2; i++) {
            int idx = i * 256 + tid;
            int dd  = idx >> 4;
            int e4  = idx & 15;
            float4 v = *(const float4*)(wb + (size_t)(kt + dd) * DH + e4 * 4);
            uint4 u = make_uint4(f2tf(v.x), f2tf(v.y), f2tf(v.z), f2tf(v.w));
            *(uint4*)&sW[dd * 72 + e4 * 4] = u;
        }
        __syncthreads();

#pragma unroll
        for (int ks = 0; ks < 4; ks++) {
            const int k0 = ks * 8;
            unsigned a[2][4];
#pragma unroll
            for (int mt = 0; mt < 2; mt++) {
                const int r = rb + mt * 16 + grp;
                a[mt][0] = sX[(k0 + tig) * 264 + r];
                a[mt][1] = sX[(k0 + tig) * 264 + r + 8];
                a[mt][2] = sX[(k0 + tig + 4) * 264 + r];
                a[mt][3] = sX[(k0 + tig + 4) * 264 + r + 8];
            }
#pragma unroll
            for (int nt = 0; nt < 8; nt++) {
                unsigned b0 = sW[(k0 + tig) * 72 + nt * 8 + grp];
                unsigned b1 = sW[(k0 + tig + 4) * 72 + nt * 8 + grp];
                mma8(acc[0][nt], a[0][0], a[0][1], a[0][2], a[0][3], b0, b1);
                mma8(acc[1][nt], a[1][0], a[1][1], a[1][2], a[1][3], b0, b1);
            }
        }
        __syncthreads();
    }

    if (n < 2) {
#pragma unroll
        for (int mt = 0; mt < 2; mt++) {
            float slo = 0.f, shi = 0.f;
#pragma unroll
            for (int nt = 0; nt < 8; nt++) {
                slo += acc[mt][nt][0] + acc[mt][nt][1];
                shi += acc[mt][nt][2] + acc[mt][nt][3];
            }
            slo += __shfl_xor_sync(~0u, slo, 1); slo += __shfl_xor_sync(~0u, slo, 2);
            shi += __shfl_xor_sync(~0u, shi, 1); shi += __shfl_xor_sync(~0u, shi, 2);
            float mlo = slo * (1.f / 64.f), mhi = shi * (1.f / 64.f);
            float vlo = 0.f, vhi = 0.f;
#pragma unroll
            for (int nt = 0; nt < 8; nt++) {
                float d0 = acc[mt][nt][0] - mlo, d1 = acc[mt][nt][1] - mlo;
                float d2 = acc[mt][nt][2] - mhi, d3 = acc[mt][nt][3] - mhi;
                vlo += d0 * d0 + d1 * d1;
                vhi += d2 * d2 + d3 * d3;
            }
            vlo += __shfl_xor_sync(~0u, vlo, 1); vlo += __shfl_xor_sync(~0u, vlo, 2);
            vhi += __shfl_xor_sync(~0u, vhi, 1); vhi += __shfl_xor_sync(~0u, vhi, 2);
            float ilo = 1.f / (sqrtf(vlo * (1.f / 63.f)) + 1e-5f);
            float ihi = 1.f / (sqrtf(vhi * (1.f / 63.f)) + 1e-5f);
#pragma unroll
            for (int nt = 0; nt < 8; nt++) {
                acc[mt][nt][0] = (acc[mt][nt][0] - mlo) * ilo;
                acc[mt][nt][1] = (acc[mt][nt][1] - mlo) * ilo;
                acc[mt][nt][2] = (acc[mt][nt][2] - mhi) * ihi;
                acc[mt][nt][3] = (acc[mt][nt][3] - mhi) * ihi;
            }
        }
    }

    float* dst = g_qkv + (((size_t)n * BSZ + b) * NH + hh) * (size_t)TT * DH;
    if (n == 1) {
        // K stored TRANSPOSED: [e][t]  (4 sectors per store instr — fine)
#pragma unroll
        for (int mt = 0; mt < 2; mt++) {
            const int rlo = t0 + rb + mt * 16 + grp;
            const int rhi = rlo + 8;
#pragma unroll
            for (int nt = 0; nt < 8; nt++) {
                int e = nt * 8 + 2 * tig;
                dst[(size_t)e * TT + rlo]       = __uint_as_float(f2tf(acc[mt][nt][0]));
                dst[(size_t)(e + 1) * TT + rlo] = __uint_as_float(f2tf(acc[mt][nt][1]));
                dst[(size_t)e * TT + rhi]       = __uint_as_float(f2tf(acc[mt][nt][2]));
                dst[(size_t)(e + 1) * TT + rhi] = __uint_as_float(f2tf(acc[mt][nt][3]));
            }
        }
    } else {
#pragma unroll
        for (int mt = 0; mt < 2; mt++) {
            const int rlo = t0 + rb + mt * 16 + grp;
            const int rhi = rlo + 8;
#pragma unroll
            for (int nt = 0; nt < 8; nt++) {
                int e = nt * 8 + 2 * tig;
                *(float2*)(dst + (size_t)rlo * DH + e) =
                    make_float2(__uint_as_float(f2tf(acc[mt][nt][0])),
                                __uint_as_float(f2tf(acc[mt][nt][1])));
                *(float2*)(dst + (size_t)rhi * DH + e) =
                    make_float2(__uint_as_float(f2tf(acc[mt][nt][2])),
                                __uint_as_float(f2tf(acc[mt][nt][3])));
            }
        }
    }
}

// ============================================================================
// Kernel 2: flash attention, no-max softmax, conflict-free LDS.128 B-operands.
// grid (T/128, B*H), 256 threads, 2 blocks/SM.
// sKT: K^T tile [d][pos(s)], sV: V tile [s][pos(e)] — one uint4 = 4 nt B-frags.
// sP: stride 64, XOR-swizzled (stores 2wf, loads 1wf).
// ============================================================================
#define SMEM2_WORDS (128 * 68 + 64 * 64 + 64 * 64 + 128 * 64)

__global__ __launch_bounds__(256, 2) void attn_kernel(float* __restrict__ out) {
    extern __shared__ unsigned sm[];
    unsigned* sQ  = sm;                // [128][68]
    unsigned* sKT = sQ + 128 * 68;     // [64][64] permuted+swizzled
    unsigned* sV  = sKT + 64 * 64;     // [64][64] permuted+swizzled
    unsigned* sP  = sV + 64 * 64;      // [128][64] swizzled

    const int t0 = blockIdx.x * 128;
    const int b  = blockIdx.y >> 4;
    const int hh = blockIdx.y & 15;

    const size_t base = (((size_t)b) * NH + hh) * (size_t)TT * DH;
    const size_t pl   = (size_t)BSZ * NH * TT * DH;
    const float* Qg = g_qkv + base;            // [T][64]
    const float* Kg = g_qkv + pl + base;       // TRANSPOSED [64][T]
    const float* Vg = g_qkv + 2 * pl + base;   // [T][64]

    const int tid  = threadIdx.x;
    const int lane = tid & 31;
    const int wid  = tid >> 5;
    const int grp  = lane >> 2;
    const int tig  = lane & 3;
    const int rb   = wid * 16;

    // load Q tile once: 128x64 uint4 (already tf32 bits)
    {
        const uint4* Qg4 = (const uint4*)(Qg + (size_t)t0 * DH);
#pragma unroll
        for (int i = 0; i < 8; i++) {
            int idx = i * 256 + tid;
            int r = idx >> 4, e4 = idx & 15;
            *(uint4*)&sQ[r * 68 + e4 * 4] = Qg4[idx];
        }
    }

    float o[8][4];
#pragma unroll
    for (int nt = 0; nt < 8; nt++) { o[nt][0] = o[nt][1] = o[nt][2] = o[nt][3] = 0.f; }
    float llo = 0.f, lhi = 0.f;

    // B-fragment base position for this lane (bits [2:6) of pos; c2 = low 2 bits)
    const int pbase0 = ((grp >> 1) << 2) | ((grp & 1) << 4);          // ntBlk 0
    const int pbase1 = pbase0 | (1 << 5);                              // ntBlk 1

    for (int s0 = 0; s0 < TT; s0 += 64) {
        // ---- stage K^T tile: rows d 0..63, cols s0..s0+63, scatter to perm pos
        {
#pragma unroll
            for (int i = 0; i < 4; i++) {
                int idx = i * 256 + tid;
                int d = idx >> 4, s4 = idx & 15;
                uint4 v = *(const uint4*)(Kg + (size_t)d * TT + s0 + s4 * 4);
                unsigned* row = &sKT[d * 64];
                int key = (d & 3) << 2;
                row[qperm(4 * s4 + 0) ^ key] = v.x;
                row[qperm(4 * s4 + 1) ^ key] = v.y;
                row[qperm(4 * s4 + 2) ^ key] = v.z;
                row[qperm(4 * s4 + 3) ^ key] = v.w;
            }
        }
        // ---- stage V tile: rows s 0..63, cols e permuted
        {
#pragma unroll
            for (int i = 0; i < 4; i++) {
                int idx = i * 256 + tid;
                int sl = idx >> 4, e4 = idx & 15;
                uint4 v = *(const uint4*)(Vg + (size_t)(s0 + sl) * DH + e4 * 4);
                unsigned* row = &sV[sl * 64];
                int key = (sl & 3) << 2;
                row[qperm(4 * e4 + 0) ^ key] = v.x;
                row[qperm(4 * e4 + 1) ^ key] = v.y;
                row[qperm(4 * e4 + 2) ^ key] = v.z;
                row[qperm(4 * e4 + 3) ^ key] = v.w;
            }
        }
        __syncthreads();  // tiles visible (first iter: also covers Q load)

        // ---- S = Q K^T  (16 rows x 64 s-cols per warp)
        float sa[8][4];
#pragma unroll
        for (int nt = 0; nt < 8; nt++) { sa[nt][0] = sa[nt][1] = sa[nt][2] = sa[nt][3] = 0.f; }
#pragma unroll
        for (int ks = 0; ks < 8; ks++) {
            const int k0 = ks * 8;
            unsigned a0 = sQ[(rb + grp) * 68 + k0 + tig];
            unsigned a1 = sQ[(rb + grp + 8) * 68 + k0 + tig];
            unsigned a2 = sQ[(rb + grp) * 68 + k0 + tig + 4];
            unsigned a3 = sQ[(rb + grp + 8) * 68 + k0 + tig + 4];
            // 4 LDS.128: (h=b0/b1) x (ntBlk) — each delivers 4 nt fragments
            unsigned kb[4][4];
#pragma unroll
            for (int h = 0; h < 2; h++) {
                int row = k0 + tig + 4 * h;          // row&3 == tig
                int xk = (tig << 2);
                *(uint4*)kb[h * 2 + 0] = *(const uint4*)&sKT[row * 64 + (pbase0 ^ xk)];
                *(uint4*)kb[h * 2 + 1] = *(const uint4*)&sKT[row * 64 + (pbase1 ^ xk)];
            }
#pragma unroll
            for (int nt = 0; nt < 8; nt++) {
                mma8(sa[nt], a0, a1, a2, a3,
                     kb[0 + (nt >> 2) * 0 + (nt >> 2) * 1 * 1][0] * 0 + kb[(nt >> 2)][nt & 3],
                     kb[2 + (nt >> 2)][nt & 3]);
            }
        }

        // ---- unshifted softmax (scale 1/8); P -> sP (swizzled)
        float rslo = 0.f, rshi = 0.f;
#pragma unroll
        for (int nt = 0; nt < 8; nt++) {
            sa[nt][0] = __expf(sa[nt][0] * 0.125f);
            sa[nt][1] = __expf(sa[nt][1] * 0.125f);
            sa[nt][2] = __expf(sa[nt][2] * 0.125f);
            sa[nt][3] = __expf(sa[nt][3] * 0.125f);
            rslo += sa[nt][0] + sa[nt][1];
            rshi += sa[nt][2] + sa[nt][3];
            int sc = nt * 8 + 2 * tig;
            int xp = (grp & 3) << 3;
            *(uint2*)&sP[(rb + grp) * 64 + (sc ^ xp)] =
                make_uint2(__float_as_uint(sa[nt][0]), __float_as_uint(sa[nt][1]));
            *(uint2*)&sP[(rb + grp + 8) * 64 + (sc ^ xp)] =
                make_uint2(__float_as_uint(sa[nt][2]), __float_as_uint(sa[nt][3]));
        }
        rslo += __shfl_xor_sync(~0u, rslo, 1); rslo += __shfl_xor_sync(~0u, rslo, 2);
        rshi += __shfl_xor_sync(~0u, rshi, 1); rshi += __shfl_xor_sync(~0u, rshi, 2);
        llo += rslo;
        lhi += rshi;
        __syncwarp();

        // ---- O += P V
#pragma unroll
        for (int ks = 0; ks < 8; ks++) {
            const int k0 = ks * 8;
            int xp = (grp & 3) << 3;
            unsigned a0 = sP[(rb + grp) * 64 + ((k0 + tig) ^ xp)];
            unsigned a1 = sP[(rb + grp + 8) * 64 + ((k0 + tig) ^ xp)];
            unsigned a2 = sP[(rb + grp) * 64 + ((k0 + tig + 4) ^ xp)];
            unsigned a3 = sP[(rb + grp + 8) * 64 + ((k0 + tig + 4) ^ xp)];
            unsigned vb[4][4];
#pragma unroll
            for (int h = 0; h < 2; h++) {
                int row = k0 + tig + 4 * h;
                int xk = (tig << 2);
                *(uint4*)vb[h * 2 + 0] = *(const uint4*)&sV[row * 64 + (pbase0 ^ xk)];
                *(uint4*)vb[h * 2 + 1] = *(const uint4*)&sV[row * 64 + (pbase1 ^ xk)];
            }
#pragma unroll
            for (int nt = 0; nt < 8; nt++) {
                mma8(o[nt], a0, a1, a2, a3, vb[(nt >> 2)][nt & 3], vb[2 + (nt >> 2)][nt & 3]);
            }
        }
        __syncthreads();  // all warps done with sKT/sV before next overwrite
    }

    // epilogue: divide by l, write transposed out[b, h*64+e, t]
    float ilo = 1.f / llo, ihi = 1.f / lhi;
    float* ob = out + ((size_t)b * DD + hh * DH) * TT;
    const int rlo = t0 + rb + grp;
    const int rhi = rlo + 8;
#pragma unroll
    for (int nt = 0; nt < 8; nt++) {
        int e = nt * 8 + 2 * tig;
        ob[(size_t)e * TT + rlo]       = o[nt][0] * ilo;
        ob[(size_t)(e + 1) * TT + rlo] = o[nt][1] * ilo;
        ob[(size_t)e * TT + rhi]       = o[nt][2] * ihi;
        ob[(size_t)(e + 1) * TT + rhi] = o[nt][3] * ihi;
    }
}

extern "C" void kernel_launch(void* const* d_in, const int* in_sizes, int n_in,
                              void* d_out, int out_size) {
    (void)in_sizes; (void)n_in; (void)out_size;
    const float* x   = (const float*)d_in[0];   // [4,1024,2048] fp32
    const float* qkv = (const float*)d_in[1];   // [3,16,1024,64] fp32
    float* out = (float*)d_out;                 // [4,1024,2048] fp32

    qkv_proj_kernel<<<dim3(TT / 256, 3 * BSZ * NH), 256>>>(x, qkv);

    const int smem2 = SMEM2_WORDS * 4;  // 100352 B -> 2 blocks/SM
    cudaFuncSetAttribute(attn_kernel, cudaFuncAttributeMaxDynamicSharedMemorySize, smem2);
    attn_kernel<<<dim3(TT / 128, BSZ * NH), 256, smem2>>>(out);
}